// round 15
// baseline (speedup 1.0000x reference)
#include <cuda_runtime.h>
#include <cuda_bf16.h>
#include <math.h>
#include <stdint.h>

#define BSZ 4
#define SSZ 2048
#define ESZ 1024
#define HSZ 16
#define DSZ 64

#define QPAD 68    // attn: Q staging stride (fp32)
#define KPADF 68   // attn: K smem stride (tf32 words)
#define PPADB 72   // attn: P smem stride (bf16)
#define VPADB 72   // attn: V smem stride (bf16)

// Attention double-buffer smem layout (bytes)
#define A_STG   35840
#define A_VHI   17408
#define A_VLO   26624
#define A_PHI   71680
#define A_PLO   90112
#define A_TOTAL 108544

// GEMM 3-stage smem layout (bytes within one stage)
#define GS_ALO   10240   // Ahi [128][80B] then Alo
#define GS_BHI   20480   // Bhi [32][528B]
#define GS_BLO   37376
#define GS_STG   54272
#define GS_TOTAL 162816  // 3 stages

// Scratch (allocation-free)
__device__ float g_q[BSZ*HSZ*SSZ*DSZ];
__device__ float g_k[BSZ*HSZ*SSZ*DSZ];
__device__ float g_v[BSZ*HSZ*SSZ*DSZ];
__device__ __nv_bfloat16 g_attnHi[BSZ*SSZ*HSZ*DSZ];
__device__ __nv_bfloat16 g_attnLo[BSZ*SSZ*HSZ*DSZ];
__device__ __nv_bfloat16 g_hidHi[BSZ*SSZ*ESZ];
__device__ __nv_bfloat16 g_hidLo[BSZ*SSZ*ESZ];
__device__ __nv_bfloat16 g_wqkvHi[ESZ*3*HSZ*DSZ];
__device__ __nv_bfloat16 g_wqkvLo[ESZ*3*HSZ*DSZ];
__device__ __nv_bfloat16 g_wprojHi[HSZ*DSZ*ESZ];
__device__ __nv_bfloat16 g_wprojLo[HSZ*DSZ*ESZ];

__device__ __forceinline__ uint32_t f2tf32(float x) {
    uint32_t r;
    asm("cvt.rna.tf32.f32 %0, %1;" : "=r"(r) : "f"(x));
    return r;
}

__device__ __forceinline__ void mma_tf32(float& d0, float& d1, float& d2, float& d3,
                                         uint32_t a0, uint32_t a1, uint32_t a2, uint32_t a3,
                                         uint32_t b0, uint32_t b1) {
    asm volatile(
        "mma.sync.aligned.m16n8k8.row.col.f32.tf32.tf32.f32 "
        "{%0,%1,%2,%3},{%4,%5,%6,%7},{%8,%9},{%0,%1,%2,%3};"
        : "+f"(d0), "+f"(d1), "+f"(d2), "+f"(d3)
        : "r"(a0), "r"(a1), "r"(a2), "r"(a3), "r"(b0), "r"(b1));
}

__device__ __forceinline__ void mma_bf16(float& d0, float& d1, float& d2, float& d3,
                                         uint32_t a0, uint32_t a1, uint32_t a2, uint32_t a3,
                                         uint32_t b0, uint32_t b1) {
    asm volatile(
        "mma.sync.aligned.m16n8k16.row.col.f32.bf16.bf16.f32 "
        "{%0,%1,%2,%3},{%4,%5,%6,%7},{%8,%9},{%0,%1,%2,%3};"
        : "+f"(d0), "+f"(d1), "+f"(d2), "+f"(d3)
        : "r"(a0), "r"(a1), "r"(a2), "r"(a3), "r"(b0), "r"(b1));
}

__device__ __forceinline__ void bsplit2(float x0, float x1, uint32_t& hi, uint32_t& lo) {
    uint32_t h;
    asm("cvt.rn.bf16x2.f32 %0, %1, %2;" : "=r"(h) : "f"(x1), "f"(x0));
    float h1 = __uint_as_float(h & 0xFFFF0000u);
    float h0 = __uint_as_float(h << 16);
    float r0 = x0 - h0;
    float r1 = x1 - h1;
    asm("cvt.rn.bf16x2.f32 %0, %1, %2;" : "=r"(lo) : "f"(r1), "f"(r0));
    hi = h;
}

__device__ __forceinline__ void ldsm_x4(uint32_t& r0, uint32_t& r1, uint32_t& r2, uint32_t& r3,
                                        uint32_t addr) {
    asm volatile("ldmatrix.sync.aligned.m8n8.x4.shared.b16 {%0,%1,%2,%3}, [%4];"
        : "=r"(r0), "=r"(r1), "=r"(r2), "=r"(r3) : "r"(addr));
}
__device__ __forceinline__ void ldsm_x4_t(uint32_t& r0, uint32_t& r1, uint32_t& r2, uint32_t& r3,
                                          uint32_t addr) {
    asm volatile("ldmatrix.sync.aligned.m8n8.x4.trans.shared.b16 {%0,%1,%2,%3}, [%4];"
        : "=r"(r0), "=r"(r1), "=r"(r2), "=r"(r3) : "r"(addr));
}

__device__ __forceinline__ void cpa16(uint32_t dst, const void* src) {
    asm volatile("cp.async.cg.shared.global [%0], [%1], 16;"
        :: "r"(dst), "l"(__cvta_generic_to_global(src)));
}
#define CPA_COMMIT() asm volatile("cp.async.commit_group;" ::: "memory")
#define CPA_WAIT(n)  asm volatile("cp.async.wait_group %0;" :: "n"(n) : "memory")

// ---------------------------------------------------------------------------
// Pre-split: fp32 -> bf16 hi/lo device arrays. which: 0=hidden 1=Wqkv 2=Wproj
// ---------------------------------------------------------------------------
__global__ __launch_bounds__(256) void split_kernel(const float4* __restrict__ src,
                                                    int which, int n4)
{
    __nv_bfloat16 *hiA, *loA;
    if (which == 0)      { hiA = g_hidHi;  loA = g_hidLo;  }
    else if (which == 1) { hiA = g_wqkvHi; loA = g_wqkvLo; }
    else                 { hiA = g_wprojHi; loA = g_wprojLo; }
    int i = blockIdx.x * 256 + threadIdx.x;
    if (i < n4) {
        float4 v = src[i];
        uint32_t h0, l0, h1, l1;
        bsplit2(v.x, v.y, h0, l0);
        bsplit2(v.z, v.w, h1, l1);
        ((uint2*)hiA)[i] = make_uint2(h0, h1);
        ((uint2*)loA)[i] = make_uint2(l0, l1);
    }
}

// ---------------------------------------------------------------------------
// 3xBF16 GEMM, R14: pre-split operands, cp.async 3-stage ring (1 sync/chunk),
// BM=128, BN=256, warp tile 64x64 (2m x 4n), 256 threads.
// mode 0: A=g_hid*, B=g_wqkv*, N=3072, scatter to g_q/k/v with q-scale
// mode 1: A=g_attn*, B=g_wproj*, N=1024, write out
// ---------------------------------------------------------------------------
__global__ __launch_bounds__(256) void gemm_tc_kernel(
    const float* __restrict__ bias, float* __restrict__ out,
    const int* __restrict__ lidx, int N, int mode)
{
    const int K = 1024;
    extern __shared__ char smg[];
    uint32_t smB = (uint32_t)__cvta_generic_to_shared(smg);

    const __nv_bfloat16* Ahi = mode ? g_attnHi : g_hidHi;
    const __nv_bfloat16* Alo = mode ? g_attnLo : g_hidLo;
    const __nv_bfloat16* Bhi = mode ? g_wprojHi : g_wqkvHi;
    const __nv_bfloat16* Blo = mode ? g_wprojLo : g_wqkvLo;

    int tid = threadIdx.x;
    int bm = blockIdx.y;
    int bn = blockIdx.x;
    int lane = tid & 31, warp = tid >> 5;
    int wm = (warp >> 2) * 64;      // 2 m-warps, 64 rows each
    int wn = (warp & 3) * 64;       // 4 n-warps, 64 cols each
    int r = lane >> 2;
    int c = lane & 3;

    int lr   = lane & 7;
    int lm8  = (lane >> 3) & 1;
    int lhi  = (lane >> 4) & 1;
    int aRowL = wm + lr + lm8 * 8;
    int bRowL = lr + lm8 * 8;

    // cp.async assignments
    int aIdx = tid * 2;             // A: 512 x 16B per buffer; 2/thread
    int aRow = aIdx >> 2, aSeg0 = (aIdx & 3);
    int bIdx = tid * 4;             // B: 1024 x 16B per buffer; 4/thread
    int bRow = bIdx >> 5, bSeg0 = (bIdx & 31);

    auto issueChunk = [&](int cI, int s) {
        uint32_t st = smB + (uint32_t)s * GS_STG;
        int k0 = cI * 32;
        #pragma unroll
        for (int j = 0; j < 2; j++) {
            int seg = aSeg0 + j;
            size_t go = (size_t)(bm * 128 + aRow) * 1024 + k0 + seg * 8;
            uint32_t so = (uint32_t)aRow * 80u + (uint32_t)seg * 16u;
            cpa16(st + so, Ahi + go);
            cpa16(st + GS_ALO + so, Alo + go);
        }
        #pragma unroll
        for (int j = 0; j < 4; j++) {
            int seg = bSeg0 + j;
            size_t go = (size_t)(k0 + bRow) * N + bn * 256 + seg * 8;
            uint32_t so = (uint32_t)bRow * 528u + (uint32_t)seg * 16u;
            cpa16(st + GS_BHI + so, Bhi + go);
            cpa16(st + GS_BLO + so, Blo + go);
        }
    };

    float acc[4][8][4];
    #pragma unroll
    for (int mi = 0; mi < 4; mi++)
        #pragma unroll
        for (int ni = 0; ni < 8; ni++)
            #pragma unroll
            for (int e = 0; e < 4; e++) acc[mi][ni][e] = 0.f;

    issueChunk(0, 0); CPA_COMMIT();
    issueChunk(1, 1); CPA_COMMIT();

    const int NCHUNK = K / 32;      // 32
    int stage = 0;
    for (int cI = 0; cI < NCHUNK; cI++) {
        if (cI < NCHUNK - 1) { CPA_WAIT(1); } else { CPA_WAIT(0); }
        __syncthreads();
        if (cI + 2 < NCHUNK) {
            int s2 = stage + 2; if (s2 >= 3) s2 -= 3;
            issueChunk(cI + 2, s2);
            CPA_COMMIT();
        }

        uint32_t stO = smB + (uint32_t)stage * GS_STG;
        #pragma unroll
        for (int ks = 0; ks < 2; ks++) {
            uint32_t ahi[4][4], alo[4][4];
            #pragma unroll
            for (int mi = 0; mi < 4; mi++) {
                uint32_t off = (uint32_t)(aRowL + mi * 16) * 80u + ks * 32u + lhi * 16u;
                ldsm_x4(ahi[mi][0], ahi[mi][1], ahi[mi][2], ahi[mi][3], stO + off);
                ldsm_x4(alo[mi][0], alo[mi][1], alo[mi][2], alo[mi][3], stO + GS_ALO + off);
            }
            #pragma unroll
            for (int p = 0; p < 4; p++) {
                uint32_t bhi[4], blo[4];
                uint32_t off = (uint32_t)(ks * 16 + bRowL) * 528u
                             + (uint32_t)(wn + p * 16 + lhi * 8) * 2u;
                ldsm_x4_t(bhi[0], bhi[1], bhi[2], bhi[3], stO + GS_BHI + off);
                ldsm_x4_t(blo[0], blo[1], blo[2], blo[3], stO + GS_BLO + off);
                #pragma unroll
                for (int mi = 0; mi < 4; mi++)
                    #pragma unroll
                    for (int q = 0; q < 2; q++) {
                        float* d = acc[mi][2 * p + q];
                        uint32_t b0h = bhi[2*q], b1h = bhi[2*q+1];
                        uint32_t b0l = blo[2*q], b1l = blo[2*q+1];
                        mma_bf16(d[0], d[1], d[2], d[3],
                                 ahi[mi][0], ahi[mi][1], ahi[mi][2], ahi[mi][3], b0h, b1h);
                        mma_bf16(d[0], d[1], d[2], d[3],
                                 ahi[mi][0], ahi[mi][1], ahi[mi][2], ahi[mi][3], b0l, b1l);
                        mma_bf16(d[0], d[1], d[2], d[3],
                                 alo[mi][0], alo[mi][1], alo[mi][2], alo[mi][3], b0h, b1h);
                    }
            }
        }
        stage++; if (stage >= 3) stage = 0;
    }

    // Epilogue. acc elem e: row = r + (e>>1)*8, col = c*2 + (e&1)
    if (mode == 0) {
        float scale = 0.125f / (float)(lidx[0] + 1);
        #pragma unroll
        for (int mi = 0; mi < 4; mi++) {
            #pragma unroll
            for (int ni = 0; ni < 8; ni++) {
                #pragma unroll
                for (int e = 0; e < 4; e++) {
                    int m = bm * 128 + wm + mi * 16 + r + (e >> 1) * 8;
                    int n = bn * 256 + wn + ni * 8 + c * 2 + (e & 1);
                    float v = acc[mi][ni][e] + bias[n];
                    int b = m >> 11, s = m & 2047;
                    int t = n >> 10;
                    int hd = n & 1023;
                    int h = hd >> 6, d = hd & 63;
                    size_t idx = ((size_t)(b * HSZ + h) * SSZ + s) * DSZ + d;
                    if (t == 0)      g_q[idx] = v * scale;
                    else if (t == 1) g_k[idx] = v;
                    else             g_v[idx] = v;
                }
            }
        }
    } else {
        #pragma unroll
        for (int mi = 0; mi < 4; mi++) {
            #pragma unroll
            for (int ni = 0; ni < 8; ni++) {
                #pragma unroll
                for (int e = 0; e < 4; e++) {
                    int m = bm * 128 + wm + mi * 16 + r + (e >> 1) * 8;
                    int n = bn * 256 + wn + ni * 8 + c * 2 + (e & 1);
                    out[(size_t)m * N + n] = acc[mi][ni][e] + bias[n];
                }
            }
        }
    }
}

// ---------------------------------------------------------------------------
// Tensor-core flash attention (R13 pipeline; epilogue now writes bf16 hi/lo).
// ---------------------------------------------------------------------------
__global__ __launch_bounds__(256, 1) void attn_tc_kernel()
{
    extern __shared__ char smc[];
    uint32_t smB = (uint32_t)__cvta_generic_to_shared(smc);

    int bh = blockIdx.y;
    int qb = 15 - blockIdx.x;
    int q0 = qb * 128;

    const float* qp = g_q + (size_t)bh * SSZ * DSZ + (size_t)q0 * DSZ;
    const float* kb = g_k + (size_t)bh * SSZ * DSZ;
    const float* vb = g_v + (size_t)bh * SSZ * DSZ;

    int tid = threadIdx.x, lane = tid & 31, warp = tid >> 5;
    int r = lane >> 2, c = lane & 3;
    int wr0 = warp * 16;
    int lr  = lane & 7;
    int lm8 = (lane >> 3) & 1;
    int lhi = (lane >> 4) & 1;
    int g   = lane >> 3;
    int kdn = (g & 1) * 8;
    int kdk = (g >> 1) * 4;

    {
        float (*Qs)[QPAD] = (float(*)[QPAD])smc;
        for (int i = tid; i < 128 * 16; i += 256) {
            int row = i >> 4, col4 = (i & 15) * 4;
            *(float4*)&Qs[row][col4] = *(const float4*)(qp + row * 64 + col4);
        }
        __syncthreads();
    }
    uint32_t qa[8][4];
    {
        float (*Qs)[QPAD] = (float(*)[QPAD])smc;
        #pragma unroll
        for (int ks = 0; ks < 8; ks++) {
            int k8 = ks * 8;
            qa[ks][0] = f2tf32(Qs[wr0 + r][k8 + c]);
            qa[ks][1] = f2tf32(Qs[wr0 + r + 8][k8 + c]);
            qa[ks][2] = f2tf32(Qs[wr0 + r][k8 + c + 4]);
            qa[ks][3] = f2tf32(Qs[wr0 + r + 8][k8 + c + 4]);
        }
        __syncthreads();
    }

    float m0 = -1e30f, m1 = -1e30f, l0 = 0.f, l1 = 0.f;
    float o[8][4];
    #pragma unroll
    for (int ni = 0; ni < 8; ni++)
        #pragma unroll
        for (int e = 0; e < 4; e++) o[ni][e] = 0.f;

    int qrow0 = q0 + wr0 + r;
    int qrow1 = qrow0 + 8;

    int rowT[4], colT[4];
    #pragma unroll
    for (int j = 0; j < 4; j++) {
        int i = tid + j * 256;
        rowT[j] = i >> 4;
        colT[j] = (i & 15) * 4;
    }

    float4 kPref[4], vPref[4];

    auto commitKV = [&](int s) {
        char* st = smc + s * A_STG;
        #pragma unroll
        for (int j = 0; j < 4; j++) {
            uint4 kt4;
            kt4.x = f2tf32(kPref[j].x); kt4.y = f2tf32(kPref[j].y);
            kt4.z = f2tf32(kPref[j].z); kt4.w = f2tf32(kPref[j].w);
            *(uint4*)(st + (uint32_t)rowT[j] * (KPADF*4) + (uint32_t)colT[j] * 4) = kt4;

            uint32_t h0, l0r, h1, l1r;
            bsplit2(vPref[j].x, vPref[j].y, h0, l0r);
            bsplit2(vPref[j].z, vPref[j].w, h1, l1r);
            *(uint2*)(st + A_VHI + (uint32_t)rowT[j] * (VPADB*2) + (uint32_t)colT[j] * 2) = make_uint2(h0, h1);
            *(uint2*)(st + A_VLO + (uint32_t)rowT[j] * (VPADB*2) + (uint32_t)colT[j] * 2) = make_uint2(l0r, l1r);
        }
    };

    {
        #pragma unroll
        for (int j = 0; j < 4; j++) {
            kPref[j] = *(const float4*)(kb + rowT[j] * 64 + colT[j]);
            vPref[j] = *(const float4*)(vb + rowT[j] * 64 + colT[j]);
        }
        commitKV(0);
    }
    __syncthreads();

    int ntiles = (qb + 1) * 2;
    for (int kt = 0; kt < ntiles; kt++) {
        if (kt + 1 < ntiles) {
            const float* kp = kb + (size_t)(kt + 1) * 64 * DSZ;
            const float* vp = vb + (size_t)(kt + 1) * 64 * DSZ;
            #pragma unroll
            for (int j = 0; j < 4; j++) {
                kPref[j] = *(const float4*)(kp + rowT[j] * 64 + colT[j]);
                vPref[j] = *(const float4*)(vp + rowT[j] * 64 + colT[j]);
            }
        }

        uint32_t stO = (uint32_t)(kt & 1) * A_STG;

        float s[8][4];
        #pragma unroll
        for (int ni = 0; ni < 8; ni++)
            #pragma unroll
            for (int e = 0; e < 4; e++) s[ni][e] = 0.f;

        #pragma unroll
        for (int ks = 0; ks < 8; ks++) {
            int k8 = ks * 8;
            #pragma unroll
            for (int np = 0; np < 4; np++) {
                uint32_t kb0, kb1, kb2, kb3;
                uint32_t off = stO + (uint32_t)((np * 16 + kdn + lr) * KPADF + k8 + kdk) * 4u;
                ldsm_x4(kb0, kb1, kb2, kb3, smB + off);
                mma_tf32(s[2*np][0], s[2*np][1], s[2*np][2], s[2*np][3],
                         qa[ks][0], qa[ks][1], qa[ks][2], qa[ks][3], kb0, kb2);
                mma_tf32(s[2*np+1][0], s[2*np+1][1], s[2*np+1][2], s[2*np+1][3],
                         qa[ks][0], qa[ks][1], qa[ks][2], qa[ks][3], kb1, kb3);
            }
        }

        if (kt * 64 + 63 > qrow0) {
            #pragma unroll
            for (int ni = 0; ni < 8; ni++) {
                int key = kt * 64 + ni * 8 + 2 * c;
                if (key     > qrow0) s[ni][0] = -1e30f;
                if (key + 1 > qrow0) s[ni][1] = -1e30f;
                if (key     > qrow1) s[ni][2] = -1e30f;
                if (key + 1 > qrow1) s[ni][3] = -1e30f;
            }
        }

        float mx0 = -1e30f, mx1 = -1e30f;
        #pragma unroll
        for (int ni = 0; ni < 8; ni++) {
            mx0 = fmaxf(mx0, fmaxf(s[ni][0], s[ni][1]));
            mx1 = fmaxf(mx1, fmaxf(s[ni][2], s[ni][3]));
        }
        mx0 = fmaxf(mx0, __shfl_xor_sync(0xffffffffu, mx0, 1));
        mx0 = fmaxf(mx0, __shfl_xor_sync(0xffffffffu, mx0, 2));
        mx1 = fmaxf(mx1, __shfl_xor_sync(0xffffffffu, mx1, 1));
        mx1 = fmaxf(mx1, __shfl_xor_sync(0xffffffffu, mx1, 2));

        float mn0 = fmaxf(m0, mx0), mn1 = fmaxf(m1, mx1);
        float sum0 = 0.f, sum1 = 0.f;
        #pragma unroll
        for (int ni = 0; ni < 8; ni++) {
            float p0 = __expf(s[ni][0] - mn0);
            float p1 = __expf(s[ni][1] - mn0);
            float p2 = __expf(s[ni][2] - mn1);
            float p3 = __expf(s[ni][3] - mn1);
            sum0 += p0 + p1;
            sum1 += p2 + p3;
            uint32_t h, lw;
            int byte0 = A_PHI + (wr0 + r) * (PPADB*2) + (ni * 8 + 2 * c) * 2;
            int byte1 = A_PHI + (wr0 + r + 8) * (PPADB*2) + (ni * 8 + 2 * c) * 2;
            bsplit2(p0, p1, h, lw);
            *(uint32_t*)(smc + byte0) = h;
            *(uint32_t*)(smc + byte0 + (A_PLO - A_PHI)) = lw;
            bsplit2(p2, p3, h, lw);
            *(uint32_t*)(smc + byte1) = h;
            *(uint32_t*)(smc + byte1 + (A_PLO - A_PHI)) = lw;
        }
        sum0 += __shfl_xor_sync(0xffffffffu, sum0, 1);
        sum0 += __shfl_xor_sync(0xffffffffu, sum0, 2);
        sum1 += __shfl_xor_sync(0xffffffffu, sum1, 1);
        sum1 += __shfl_xor_sync(0xffffffffu, sum1, 2);

        float alpha0 = __expf(m0 - mn0);
        float alpha1 = __expf(m1 - mn1);
        l0 = l0 * alpha0 + sum0;  m0 = mn0;
        l1 = l1 * alpha1 + sum1;  m1 = mn1;
        #pragma unroll
        for (int ni = 0; ni < 8; ni++) {
            o[ni][0] *= alpha0; o[ni][1] *= alpha0;
            o[ni][2] *= alpha1; o[ni][3] *= alpha1;
        }
        __syncwarp();

        #pragma unroll
        for (int ks = 0; ks < 4; ks++) {
            uint32_t phf[4], plf[4];
            uint32_t offP = A_PHI + (uint32_t)(wr0 + lr + lm8 * 8) * (PPADB*2)
                          + (uint32_t)(ks * 16 + lhi * 8) * 2u;
            ldsm_x4(phf[0], phf[1], phf[2], phf[3], smB + offP);
            ldsm_x4(plf[0], plf[1], plf[2], plf[3], smB + offP + (A_PLO - A_PHI));

            uint32_t vhf[4][4], vlf[4][4];
            #pragma unroll
            for (int p = 0; p < 4; p++) {
                uint32_t offV = stO + A_VHI + (uint32_t)(ks * 16 + lr + lm8 * 8) * (VPADB*2)
                              + (uint32_t)(p * 16 + lhi * 8) * 2u;
                ldsm_x4_t(vhf[p][0], vhf[p][1], vhf[p][2], vhf[p][3], smB + offV);
                ldsm_x4_t(vlf[p][0], vlf[p][1], vlf[p][2], vlf[p][3], smB + offV + (A_VLO - A_VHI));
            }
            #pragma unroll
            for (int p = 0; p < 4; p++)
                #pragma unroll
                for (int q = 0; q < 2; q++) {
                    float* d = o[2 * p + q];
                    uint32_t b0h = vhf[p][2*q], b1h = vhf[p][2*q+1];
                    uint32_t b0l = vlf[p][2*q], b1l = vlf[p][2*q+1];
                    mma_bf16(d[0], d[1], d[2], d[3],
                             phf[0], phf[1], phf[2], phf[3], b0h, b1h);
                    mma_bf16(d[0], d[1], d[2], d[3],
                             phf[0], phf[1], phf[2], phf[3], b0l, b1l);
                    mma_bf16(d[0], d[1], d[2], d[3],
                             plf[0], plf[1], plf[2], plf[3], b0h, b1h);
                }
        }

        if (kt + 1 < ntiles)
            commitKV((kt + 1) & 1);
        __syncthreads();
    }

    // Epilogue: normalize and write pre-split bf16 hi/lo [B][S][H][D]
    int b = bh >> 4, h = bh & 15;
    float inv0 = 1.f / l0, inv1 = 1.f / l1;
    int s0 = q0 + wr0 + r, s1 = s0 + 8;
    size_t base0 = ((size_t)(b * SSZ + s0) * HSZ + h) * DSZ;
    size_t base1 = ((size_t)(b * SSZ + s1) * HSZ + h) * DSZ;
    #pragma unroll
    for (int ni = 0; ni < 8; ni++) {
        int d0 = ni * 8 + 2 * c;
        uint32_t hh, ll;
        bsplit2(o[ni][0] * inv0, o[ni][1] * inv0, hh, ll);
        *(uint32_t*)(g_attnHi + base0 + d0) = hh;
        *(uint32_t*)(g_attnLo + base0 + d0) = ll;
        bsplit2(o[ni][2] * inv1, o[ni][3] * inv1, hh, ll);
        *(uint32_t*)(g_attnHi + base1 + d0) = hh;
        *(uint32_t*)(g_attnLo + base1 + d0) = ll;
    }
}

extern "C" void kernel_launch(void* const* d_in, const int* in_sizes, int n_in,
                              void* d_out, int out_size)
{
    const float* hidden = (const float*)d_in[0];
    const float* Wqkv  = (const float*)d_in[2];
    const float* bqkv  = (const float*)d_in[3];
    const float* Wproj = (const float*)d_in[4];
    const float* bproj = (const float*)d_in[5];
    const int*   lidx  = (const int*)d_in[6];
    float* out = (float*)d_out;

    cudaFuncSetAttribute(gemm_tc_kernel,
        cudaFuncAttributeMaxDynamicSharedMemorySize, GS_TOTAL);
    cudaFuncSetAttribute(attn_tc_kernel,
        cudaFuncAttributeMaxDynamicSharedMemorySize, A_TOTAL);

    // Pre-split operands into bf16 hi/lo
    split_kernel<<<8192, 256>>>((const float4*)hidden, 0, 2097152);
    split_kernel<<<3072, 256>>>((const float4*)Wqkv, 1, 786432);
    split_kernel<<<1024, 256>>>((const float4*)Wproj, 2, 262144);

    // QKV projection: M=8192, N=3072, K=1024  (BN=256 -> 12 n-blocks)
    gemm_tc_kernel<<<dim3(12, 64), 256, GS_TOTAL>>>(bqkv, nullptr, lidx, 3072, 0);
    // Attention: 16 query tiles (128 rows each) x 64 (b,h) pairs
    attn_tc_kernel<<<dim3(16, 64), 256, A_TOTAL>>>();
    // Output projection: M=8192, N=1024, K=1024  (BN=256 -> 4 n-blocks)
    gemm_tc_kernel<<<dim3(4, 64), 256, GS_TOTAL>>>(bproj, out, lidx, 1024, 1);
}

// round 16
// speedup vs baseline: 1.0486x; 1.0486x over previous
#include <cuda_runtime.h>
#include <cuda_bf16.h>
#include <math.h>
#include <stdint.h>

#define BSZ 4
#define SSZ 2048
#define ESZ 1024
#define HSZ 16
#define DSZ 64

#define QPAD 68    // attn: Q staging stride (fp32)
#define KPADF 68   // attn: K smem stride (tf32 words)
#define PPADB 72   // attn: P smem stride (bf16)
#define VPADB 72   // attn: V smem stride (bf16)

// Attention double-buffer smem layout (bytes)
#define A_STG   35840
#define A_VHI   17408
#define A_VLO   26624
#define A_PHI   71680
#define A_PLO   90112
#define A_TOTAL 108544

// GEMM double-buffer smem layout (bytes within one stage)
#define G_ALO   10240   // Ahi [128][80B] then Alo
#define G_BHI   20480   // Bhi [32][272B]
#define G_BLO   29184
#define G_STG   37888
#define G_TOTAL 75776

// Scratch (allocation-free)
__device__ float g_q[BSZ*HSZ*SSZ*DSZ];
__device__ float g_k[BSZ*HSZ*SSZ*DSZ];
__device__ float g_v[BSZ*HSZ*SSZ*DSZ];
__device__ __nv_bfloat16 g_attnHi[BSZ*SSZ*HSZ*DSZ];
__device__ __nv_bfloat16 g_attnLo[BSZ*SSZ*HSZ*DSZ];
__device__ __nv_bfloat16 g_hidHi[BSZ*SSZ*ESZ];
__device__ __nv_bfloat16 g_hidLo[BSZ*SSZ*ESZ];
__device__ __nv_bfloat16 g_wqkvHi[ESZ*3*HSZ*DSZ];
__device__ __nv_bfloat16 g_wqkvLo[ESZ*3*HSZ*DSZ];
__device__ __nv_bfloat16 g_wprojHi[HSZ*DSZ*ESZ];
__device__ __nv_bfloat16 g_wprojLo[HSZ*DSZ*ESZ];

__device__ __forceinline__ uint32_t f2tf32(float x) {
    uint32_t r;
    asm("cvt.rna.tf32.f32 %0, %1;" : "=r"(r) : "f"(x));
    return r;
}

__device__ __forceinline__ void mma_tf32(float& d0, float& d1, float& d2, float& d3,
                                         uint32_t a0, uint32_t a1, uint32_t a2, uint32_t a3,
                                         uint32_t b0, uint32_t b1) {
    asm volatile(
        "mma.sync.aligned.m16n8k8.row.col.f32.tf32.tf32.f32 "
        "{%0,%1,%2,%3},{%4,%5,%6,%7},{%8,%9},{%0,%1,%2,%3};"
        : "+f"(d0), "+f"(d1), "+f"(d2), "+f"(d3)
        : "r"(a0), "r"(a1), "r"(a2), "r"(a3), "r"(b0), "r"(b1));
}

__device__ __forceinline__ void mma_bf16(float& d0, float& d1, float& d2, float& d3,
                                         uint32_t a0, uint32_t a1, uint32_t a2, uint32_t a3,
                                         uint32_t b0, uint32_t b1) {
    asm volatile(
        "mma.sync.aligned.m16n8k16.row.col.f32.bf16.bf16.f32 "
        "{%0,%1,%2,%3},{%4,%5,%6,%7},{%8,%9},{%0,%1,%2,%3};"
        : "+f"(d0), "+f"(d1), "+f"(d2), "+f"(d3)
        : "r"(a0), "r"(a1), "r"(a2), "r"(a3), "r"(b0), "r"(b1));
}

__device__ __forceinline__ void bsplit2(float x0, float x1, uint32_t& hi, uint32_t& lo) {
    uint32_t h;
    asm("cvt.rn.bf16x2.f32 %0, %1, %2;" : "=r"(h) : "f"(x1), "f"(x0));
    float h1 = __uint_as_float(h & 0xFFFF0000u);
    float h0 = __uint_as_float(h << 16);
    float r0 = x0 - h0;
    float r1 = x1 - h1;
    asm("cvt.rn.bf16x2.f32 %0, %1, %2;" : "=r"(lo) : "f"(r1), "f"(r0));
    hi = h;
}

__device__ __forceinline__ void ldsm_x4(uint32_t& r0, uint32_t& r1, uint32_t& r2, uint32_t& r3,
                                        uint32_t addr) {
    asm volatile("ldmatrix.sync.aligned.m8n8.x4.shared.b16 {%0,%1,%2,%3}, [%4];"
        : "=r"(r0), "=r"(r1), "=r"(r2), "=r"(r3) : "r"(addr));
}
__device__ __forceinline__ void ldsm_x4_t(uint32_t& r0, uint32_t& r1, uint32_t& r2, uint32_t& r3,
                                          uint32_t addr) {
    asm volatile("ldmatrix.sync.aligned.m8n8.x4.trans.shared.b16 {%0,%1,%2,%3}, [%4];"
        : "=r"(r0), "=r"(r1), "=r"(r2), "=r"(r3) : "r"(addr));
}

// ---------------------------------------------------------------------------
// Pre-split: fp32 -> bf16 hi/lo device arrays. which: 0=hidden 1=Wqkv 2=Wproj
// ---------------------------------------------------------------------------
__global__ __launch_bounds__(256) void split_kernel(const float4* __restrict__ src,
                                                    int which, int n4)
{
    __nv_bfloat16 *hiA, *loA;
    if (which == 0)      { hiA = g_hidHi;  loA = g_hidLo;  }
    else if (which == 1) { hiA = g_wqkvHi; loA = g_wqkvLo; }
    else                 { hiA = g_wprojHi; loA = g_wprojLo; }
    int i = blockIdx.x * 256 + threadIdx.x;
    if (i < n4) {
        float4 v = src[i];
        uint32_t h0, l0, h1, l1;
        bsplit2(v.x, v.y, h0, l0);
        bsplit2(v.z, v.w, h1, l1);
        ((uint2*)hiA)[i] = make_uint2(h0, h1);
        ((uint2*)loA)[i] = make_uint2(l0, l1);
    }
}

// ---------------------------------------------------------------------------
// 3xBF16 GEMM, R16: R12 skeleton (reg-prefetch ping-pong, 1 sync/chunk,
// BM=128 BN=128, warp tile 64x32) fed by PRE-SPLIT bf16 hi/lo operands.
// Commit is pure STS; no cvt in the mainloop at all.
// mode 0: A=g_hid*, B=g_wqkv*, N=3072; mode 1: A=g_attn*, B=g_wproj*, N=1024.
// ---------------------------------------------------------------------------
__global__ __launch_bounds__(256) void gemm_tc_kernel(
    const float* __restrict__ bias, float* __restrict__ out,
    const int* __restrict__ lidx, int N, int mode)
{
    const int K = 1024;
    extern __shared__ char smg[];
    uint32_t smB = (uint32_t)__cvta_generic_to_shared(smg);

    const __nv_bfloat16* Ahi = mode ? g_attnHi : g_hidHi;
    const __nv_bfloat16* Alo = mode ? g_attnLo : g_hidLo;
    const __nv_bfloat16* Bhi = mode ? g_wprojHi : g_wqkvHi;
    const __nv_bfloat16* Blo = mode ? g_wprojLo : g_wqkvLo;

    int tid = threadIdx.x;
    int bm = blockIdx.y;
    int bn = blockIdx.x;
    int lane = tid & 31, warp = tid >> 5;
    int wm = (warp >> 2) * 64;      // 2 m-warps (64 rows each)
    int wn = (warp & 3) * 32;       // 4 n-warps (32 cols each)
    int r = lane >> 2;
    int c = lane & 3;

    // gmem/smem load assignment (bf16 elems)
    int aM = tid >> 1;              // 0..127
    int aK = (tid & 1) * 16;        // 0 or 16
    int bK = tid >> 3;              // 0..31
    int bN = (tid & 7) * 16;        // 0..112

    int lr   = lane & 7;
    int lm8  = (lane >> 3) & 1;
    int lhi  = (lane >> 4) & 1;
    int aRowL = wm + lr + lm8 * 8;
    int bRowL = lr + lm8 * 8;

    uint32_t aStO = (uint32_t)aM * 80u + (uint32_t)aK * 2u;
    uint32_t bStO = (uint32_t)bK * 272u + (uint32_t)bN * 2u;

    const __nv_bfloat16* AhiP = Ahi + (size_t)(bm * 128 + aM) * 1024 + aK;
    const __nv_bfloat16* AloP = Alo + (size_t)(bm * 128 + aM) * 1024 + aK;
    const __nv_bfloat16* BhiP = Bhi + (size_t)bK * N + bn * 128 + bN;
    const __nv_bfloat16* BloP = Blo + (size_t)bK * N + bn * 128 + bN;

    float acc[4][4][4];
    #pragma unroll
    for (int mi = 0; mi < 4; mi++)
        #pragma unroll
        for (int ni = 0; ni < 4; ni++)
            #pragma unroll
            for (int e = 0; e < 4; e++) acc[mi][ni][e] = 0.f;

    uint4 aH[2], aL[2], bH[2], bL[2];
    #pragma unroll
    for (int j = 0; j < 2; j++) {
        aH[j] = *(const uint4*)(AhiP + j * 8);
        aL[j] = *(const uint4*)(AloP + j * 8);
        bH[j] = *(const uint4*)(BhiP + j * 8);
        bL[j] = *(const uint4*)(BloP + j * 8);
    }

    auto commit = [&](int s) {
        char* st = smg + s * G_STG;
        *(uint4*)(st + aStO)              = aH[0];
        *(uint4*)(st + aStO + 16)         = aH[1];
        *(uint4*)(st + G_ALO + aStO)      = aL[0];
        *(uint4*)(st + G_ALO + aStO + 16) = aL[1];
        *(uint4*)(st + G_BHI + bStO)      = bH[0];
        *(uint4*)(st + G_BHI + bStO + 16) = bH[1];
        *(uint4*)(st + G_BLO + bStO)      = bL[0];
        *(uint4*)(st + G_BLO + bStO + 16) = bL[1];
    };

    commit(0);
    __syncthreads();

    const int NCHUNK = K / 32;      // 32
    for (int cI = 0; cI < NCHUNK; cI++) {
        // LDG next chunk (bf16, half the bytes of fp32 path)
        if (cI + 1 < NCHUNK) {
            int k0 = (cI + 1) * 32;
            #pragma unroll
            for (int j = 0; j < 2; j++) {
                aH[j] = *(const uint4*)(AhiP + k0 + j * 8);
                aL[j] = *(const uint4*)(AloP + k0 + j * 8);
                bH[j] = *(const uint4*)(BhiP + (size_t)k0 * N + j * 8);
                bL[j] = *(const uint4*)(BloP + (size_t)k0 * N + j * 8);
            }
        }

        uint32_t stO = smB + (uint32_t)(cI & 1) * G_STG;
        #pragma unroll
        for (int ks = 0; ks < 2; ks++) {
            uint32_t ahi[4][4], alo[4][4];
            #pragma unroll
            for (int mi = 0; mi < 4; mi++) {
                uint32_t off = (uint32_t)(aRowL + mi * 16) * 80u + ks * 32u + lhi * 16u;
                ldsm_x4(ahi[mi][0], ahi[mi][1], ahi[mi][2], ahi[mi][3], stO + off);
                ldsm_x4(alo[mi][0], alo[mi][1], alo[mi][2], alo[mi][3], stO + G_ALO + off);
            }
            uint32_t bhi[2][4], blo[2][4];
            #pragma unroll
            for (int p = 0; p < 2; p++) {
                uint32_t off = (uint32_t)(ks * 16 + bRowL) * 272u
                             + (uint32_t)(wn + p * 16 + lhi * 8) * 2u;
                ldsm_x4_t(bhi[p][0], bhi[p][1], bhi[p][2], bhi[p][3], stO + G_BHI + off);
                ldsm_x4_t(blo[p][0], blo[p][1], blo[p][2], blo[p][3], stO + G_BLO + off);
            }
            #pragma unroll
            for (int mi = 0; mi < 4; mi++)
                #pragma unroll
                for (int p = 0; p < 2; p++)
                    #pragma unroll
                    for (int q = 0; q < 2; q++) {
                        float* d = acc[mi][2 * p + q];
                        uint32_t b0h = bhi[p][2*q], b1h = bhi[p][2*q+1];
                        uint32_t b0l = blo[p][2*q], b1l = blo[p][2*q+1];
                        mma_bf16(d[0], d[1], d[2], d[3],
                                 ahi[mi][0], ahi[mi][1], ahi[mi][2], ahi[mi][3], b0h, b1h);
                        mma_bf16(d[0], d[1], d[2], d[3],
                                 ahi[mi][0], ahi[mi][1], ahi[mi][2], ahi[mi][3], b0l, b1l);
                        mma_bf16(d[0], d[1], d[2], d[3],
                                 alo[mi][0], alo[mi][1], alo[mi][2], alo[mi][3], b0h, b1h);
                    }
        }

        if (cI + 1 < NCHUNK)
            commit((cI + 1) & 1);
        __syncthreads();
    }

    // Epilogue. acc elem e: row = r + (e>>1)*8, col = c*2 + (e&1)
    if (mode == 0) {
        float scale = 0.125f / (float)(lidx[0] + 1);
        #pragma unroll
        for (int mi = 0; mi < 4; mi++) {
            #pragma unroll
            for (int ni = 0; ni < 4; ni++) {
                #pragma unroll
                for (int e = 0; e < 4; e++) {
                    int m = bm * 128 + wm + mi * 16 + r + (e >> 1) * 8;
                    int n = bn * 128 + wn + ni * 8 + c * 2 + (e & 1);
                    float v = acc[mi][ni][e] + bias[n];
                    int b = m >> 11, s = m & 2047;
                    int t = n >> 10;
                    int hd = n & 1023;
                    int h = hd >> 6, d = hd & 63;
                    size_t idx = ((size_t)(b * HSZ + h) * SSZ + s) * DSZ + d;
                    if (t == 0)      g_q[idx] = v * scale;
                    else if (t == 1) g_k[idx] = v;
                    else             g_v[idx] = v;
                }
            }
        }
    } else {
        #pragma unroll
        for (int mi = 0; mi < 4; mi++) {
            #pragma unroll
            for (int ni = 0; ni < 4; ni++) {
                #pragma unroll
                for (int e = 0; e < 4; e++) {
                    int m = bm * 128 + wm + mi * 16 + r + (e >> 1) * 8;
                    int n = bn * 128 + wn + ni * 8 + c * 2 + (e & 1);
                    out[(size_t)m * N + n] = acc[mi][ni][e] + bias[n];
                }
            }
        }
    }
}

// ---------------------------------------------------------------------------
// Tensor-core flash attention (R13 pipeline; bf16 hi/lo epilogue).
// ---------------------------------------------------------------------------
__global__ __launch_bounds__(256, 1) void attn_tc_kernel()
{
    extern __shared__ char smc[];
    uint32_t smB = (uint32_t)__cvta_generic_to_shared(smc);

    int bh = blockIdx.y;
    int qb = 15 - blockIdx.x;
    int q0 = qb * 128;

    const float* qp = g_q + (size_t)bh * SSZ * DSZ + (size_t)q0 * DSZ;
    const float* kb = g_k + (size_t)bh * SSZ * DSZ;
    const float* vb = g_v + (size_t)bh * SSZ * DSZ;

    int tid = threadIdx.x, lane = tid & 31, warp = tid >> 5;
    int r = lane >> 2, c = lane & 3;
    int wr0 = warp * 16;
    int lr  = lane & 7;
    int lm8 = (lane >> 3) & 1;
    int lhi = (lane >> 4) & 1;
    int g   = lane >> 3;
    int kdn = (g & 1) * 8;
    int kdk = (g >> 1) * 4;

    {
        float (*Qs)[QPAD] = (float(*)[QPAD])smc;
        for (int i = tid; i < 128 * 16; i += 256) {
            int row = i >> 4, col4 = (i & 15) * 4;
            *(float4*)&Qs[row][col4] = *(const float4*)(qp + row * 64 + col4);
        }
        __syncthreads();
    }
    uint32_t qa[8][4];
    {
        float (*Qs)[QPAD] = (float(*)[QPAD])smc;
        #pragma unroll
        for (int ks = 0; ks < 8; ks++) {
            int k8 = ks * 8;
            qa[ks][0] = f2tf32(Qs[wr0 + r][k8 + c]);
            qa[ks][1] = f2tf32(Qs[wr0 + r + 8][k8 + c]);
            qa[ks][2] = f2tf32(Qs[wr0 + r][k8 + c + 4]);
            qa[ks][3] = f2tf32(Qs[wr0 + r + 8][k8 + c + 4]);
        }
        __syncthreads();
    }

    float m0 = -1e30f, m1 = -1e30f, l0 = 0.f, l1 = 0.f;
    float o[8][4];
    #pragma unroll
    for (int ni = 0; ni < 8; ni++)
        #pragma unroll
        for (int e = 0; e < 4; e++) o[ni][e] = 0.f;

    int qrow0 = q0 + wr0 + r;
    int qrow1 = qrow0 + 8;

    int rowT[4], colT[4];
    #pragma unroll
    for (int j = 0; j < 4; j++) {
        int i = tid + j * 256;
        rowT[j] = i >> 4;
        colT[j] = (i & 15) * 4;
    }

    float4 kPref[4], vPref[4];

    auto commitKV = [&](int s) {
        char* st = smc + s * A_STG;
        #pragma unroll
        for (int j = 0; j < 4; j++) {
            uint4 kt4;
            kt4.x = f2tf32(kPref[j].x); kt4.y = f2tf32(kPref[j].y);
            kt4.z = f2tf32(kPref[j].z); kt4.w = f2tf32(kPref[j].w);
            *(uint4*)(st + (uint32_t)rowT[j] * (KPADF*4) + (uint32_t)colT[j] * 4) = kt4;

            uint32_t h0, l0r, h1, l1r;
            bsplit2(vPref[j].x, vPref[j].y, h0, l0r);
            bsplit2(vPref[j].z, vPref[j].w, h1, l1r);
            *(uint2*)(st + A_VHI + (uint32_t)rowT[j] * (VPADB*2) + (uint32_t)colT[j] * 2) = make_uint2(h0, h1);
            *(uint2*)(st + A_VLO + (uint32_t)rowT[j] * (VPADB*2) + (uint32_t)colT[j] * 2) = make_uint2(l0r, l1r);
        }
    };

    {
        #pragma unroll
        for (int j = 0; j < 4; j++) {
            kPref[j] = *(const float4*)(kb + rowT[j] * 64 + colT[j]);
            vPref[j] = *(const float4*)(vb + rowT[j] * 64 + colT[j]);
        }
        commitKV(0);
    }
    __syncthreads();

    int ntiles = (qb + 1) * 2;
    for (int kt = 0; kt < ntiles; kt++) {
        if (kt + 1 < ntiles) {
            const float* kp = kb + (size_t)(kt + 1) * 64 * DSZ;
            const float* vp = vb + (size_t)(kt + 1) * 64 * DSZ;
            #pragma unroll
            for (int j = 0; j < 4; j++) {
                kPref[j] = *(const float4*)(kp + rowT[j] * 64 + colT[j]);
                vPref[j] = *(const float4*)(vp + rowT[j] * 64 + colT[j]);
            }
        }

        uint32_t stO = (uint32_t)(kt & 1) * A_STG;

        float s[8][4];
        #pragma unroll
        for (int ni = 0; ni < 8; ni++)
            #pragma unroll
            for (int e = 0; e < 4; e++) s[ni][e] = 0.f;

        #pragma unroll
        for (int ks = 0; ks < 8; ks++) {
            int k8 = ks * 8;
            #pragma unroll
            for (int np = 0; np < 4; np++) {
                uint32_t kb0, kb1, kb2, kb3;
                uint32_t off = stO + (uint32_t)((np * 16 + kdn + lr) * KPADF + k8 + kdk) * 4u;
                ldsm_x4(kb0, kb1, kb2, kb3, smB + off);
                mma_tf32(s[2*np][0], s[2*np][1], s[2*np][2], s[2*np][3],
                         qa[ks][0], qa[ks][1], qa[ks][2], qa[ks][3], kb0, kb2);
                mma_tf32(s[2*np+1][0], s[2*np+1][1], s[2*np+1][2], s[2*np+1][3],
                         qa[ks][0], qa[ks][1], qa[ks][2], qa[ks][3], kb1, kb3);
            }
        }

        if (kt * 64 + 63 > qrow0) {
            #pragma unroll
            for (int ni = 0; ni < 8; ni++) {
                int key = kt * 64 + ni * 8 + 2 * c;
                if (key     > qrow0) s[ni][0] = -1e30f;
                if (key + 1 > qrow0) s[ni][1] = -1e30f;
                if (key     > qrow1) s[ni][2] = -1e30f;
                if (key + 1 > qrow1) s[ni][3] = -1e30f;
            }
        }

        float mx0 = -1e30f, mx1 = -1e30f;
        #pragma unroll
        for (int ni = 0; ni < 8; ni++) {
            mx0 = fmaxf(mx0, fmaxf(s[ni][0], s[ni][1]));
            mx1 = fmaxf(mx1, fmaxf(s[ni][2], s[ni][3]));
        }
        mx0 = fmaxf(mx0, __shfl_xor_sync(0xffffffffu, mx0, 1));
        mx0 = fmaxf(mx0, __shfl_xor_sync(0xffffffffu, mx0, 2));
        mx1 = fmaxf(mx1, __shfl_xor_sync(0xffffffffu, mx1, 1));
        mx1 = fmaxf(mx1, __shfl_xor_sync(0xffffffffu, mx1, 2));

        float mn0 = fmaxf(m0, mx0), mn1 = fmaxf(m1, mx1);
        float sum0 = 0.f, sum1 = 0.f;
        #pragma unroll
        for (int ni = 0; ni < 8; ni++) {
            float p0 = __expf(s[ni][0] - mn0);
            float p1 = __expf(s[ni][1] - mn0);
            float p2 = __expf(s[ni][2] - mn1);
            float p3 = __expf(s[ni][3] - mn1);
            sum0 += p0 + p1;
            sum1 += p2 + p3;
            uint32_t h, lw;
            int byte0 = A_PHI + (wr0 + r) * (PPADB*2) + (ni * 8 + 2 * c) * 2;
            int byte1 = A_PHI + (wr0 + r + 8) * (PPADB*2) + (ni * 8 + 2 * c) * 2;
            bsplit2(p0, p1, h, lw);
            *(uint32_t*)(smc + byte0) = h;
            *(uint32_t*)(smc + byte0 + (A_PLO - A_PHI)) = lw;
            bsplit2(p2, p3, h, lw);
            *(uint32_t*)(smc + byte1) = h;
            *(uint32_t*)(smc + byte1 + (A_PLO - A_PHI)) = lw;
        }
        sum0 += __shfl_xor_sync(0xffffffffu, sum0, 1);
        sum0 += __shfl_xor_sync(0xffffffffu, sum0, 2);
        sum1 += __shfl_xor_sync(0xffffffffu, sum1, 1);
        sum1 += __shfl_xor_sync(0xffffffffu, sum1, 2);

        float alpha0 = __expf(m0 - mn0);
        float alpha1 = __expf(m1 - mn1);
        l0 = l0 * alpha0 + sum0;  m0 = mn0;
        l1 = l1 * alpha1 + sum1;  m1 = mn1;
        #pragma unroll
        for (int ni = 0; ni < 8; ni++) {
            o[ni][0] *= alpha0; o[ni][1] *= alpha0;
            o[ni][2] *= alpha1; o[ni][3] *= alpha1;
        }
        __syncwarp();

        #pragma unroll
        for (int ks = 0; ks < 4; ks++) {
            uint32_t phf[4], plf[4];
            uint32_t offP = A_PHI + (uint32_t)(wr0 + lr + lm8 * 8) * (PPADB*2)
                          + (uint32_t)(ks * 16 + lhi * 8) * 2u;
            ldsm_x4(phf[0], phf[1], phf[2], phf[3], smB + offP);
            ldsm_x4(plf[0], plf[1], plf[2], plf[3], smB + offP + (A_PLO - A_PHI));

            uint32_t vhf[4][4], vlf[4][4];
            #pragma unroll
            for (int p = 0; p < 4; p++) {
                uint32_t offV = stO + A_VHI + (uint32_t)(ks * 16 + lr + lm8 * 8) * (VPADB*2)
                              + (uint32_t)(p * 16 + lhi * 8) * 2u;
                ldsm_x4_t(vhf[p][0], vhf[p][1], vhf[p][2], vhf[p][3], smB + offV);
                ldsm_x4_t(vlf[p][0], vlf[p][1], vlf[p][2], vlf[p][3], smB + offV + (A_VLO - A_VHI));
            }
            #pragma unroll
            for (int p = 0; p < 4; p++)
                #pragma unroll
                for (int q = 0; q < 2; q++) {
                    float* d = o[2 * p + q];
                    uint32_t b0h = vhf[p][2*q], b1h = vhf[p][2*q+1];
                    uint32_t b0l = vlf[p][2*q], b1l = vlf[p][2*q+1];
                    mma_bf16(d[0], d[1], d[2], d[3],
                             phf[0], phf[1], phf[2], phf[3], b0h, b1h);
                    mma_bf16(d[0], d[1], d[2], d[3],
                             phf[0], phf[1], phf[2], phf[3], b0l, b1l);
                    mma_bf16(d[0], d[1], d[2], d[3],
                             plf[0], plf[1], plf[2], plf[3], b0h, b1h);
                }
        }

        if (kt + 1 < ntiles)
            commitKV((kt + 1) & 1);
        __syncthreads();
    }

    // Epilogue: normalize and write pre-split bf16 hi/lo [B][S][H][D]
    int b = bh >> 4, h = bh & 15;
    float inv0 = 1.f / l0, inv1 = 1.f / l1;
    int s0 = q0 + wr0 + r, s1 = s0 + 8;
    size_t base0 = ((size_t)(b * SSZ + s0) * HSZ + h) * DSZ;
    size_t base1 = ((size_t)(b * SSZ + s1) * HSZ + h) * DSZ;
    #pragma unroll
    for (int ni = 0; ni < 8; ni++) {
        int d0 = ni * 8 + 2 * c;
        uint32_t hh, ll;
        bsplit2(o[ni][0] * inv0, o[ni][1] * inv0, hh, ll);
        *(uint32_t*)(g_attnHi + base0 + d0) = hh;
        *(uint32_t*)(g_attnLo + base0 + d0) = ll;
        bsplit2(o[ni][2] * inv1, o[ni][3] * inv1, hh, ll);
        *(uint32_t*)(g_attnHi + base1 + d0) = hh;
        *(uint32_t*)(g_attnLo + base1 + d0) = ll;
    }
}

extern "C" void kernel_launch(void* const* d_in, const int* in_sizes, int n_in,
                              void* d_out, int out_size)
{
    const float* hidden = (const float*)d_in[0];
    const float* Wqkv  = (const float*)d_in[2];
    const float* bqkv  = (const float*)d_in[3];
    const float* Wproj = (const float*)d_in[4];
    const float* bproj = (const float*)d_in[5];
    const int*   lidx  = (const int*)d_in[6];
    float* out = (float*)d_out;

    cudaFuncSetAttribute(gemm_tc_kernel,
        cudaFuncAttributeMaxDynamicSharedMemorySize, G_TOTAL);
    cudaFuncSetAttribute(attn_tc_kernel,
        cudaFuncAttributeMaxDynamicSharedMemorySize, A_TOTAL);

    // Pre-split operands into bf16 hi/lo
    split_kernel<<<8192, 256>>>((const float4*)hidden, 0, 2097152);
    split_kernel<<<3072, 256>>>((const float4*)Wqkv, 1, 786432);
    split_kernel<<<1024, 256>>>((const float4*)Wproj, 2, 262144);

    // QKV projection: M=8192, N=3072, K=1024  (BN=128 -> 24 n-blocks)
    gemm_tc_kernel<<<dim3(24, 64), 256, G_TOTAL>>>(bqkv, nullptr, lidx, 3072, 0);
    // Attention: 16 query tiles (128 rows each) x 64 (b,h) pairs
    attn_tc_kernel<<<dim3(16, 64), 256, A_TOTAL>>>();
    // Output projection: M=8192, N=1024, K=1024  (BN=128 -> 8 n-blocks)
    gemm_tc_kernel<<<dim3(8, 64), 256, G_TOTAL>>>(bproj, out, lidx, 1024, 1);
}

// round 17
// speedup vs baseline: 1.1516x; 1.0982x over previous
#include <cuda_runtime.h>
#include <cuda_bf16.h>
#include <math.h>
#include <stdint.h>

#define BSZ 4
#define SSZ 2048
#define ESZ 1024
#define HSZ 16
#define DSZ 64

#define QPAD 68    // attn: Q staging stride (fp32)
#define KPADF 68   // attn: K smem stride (tf32 words)
#define PPADB 72   // attn: P smem stride (bf16)
#define VPADB 72   // attn: V smem stride (bf16)

// Attention double-buffer smem layout (bytes)
#define A_STG   35840
#define A_VHI   17408
#define A_VLO   26624
#define A_PHI   71680
#define A_PLO   90112
#define A_TOTAL 108544

// GEMM double-buffer smem layout (bytes within one stage)
#define G_ALO   10240   // Ahi [128][80B] then Alo
#define G_BHI   20480   // Bhi [32][528B]
#define G_BLO   37376
#define G_STG   54272
#define G_TOTAL 108544

// Scratch (allocation-free): Q/K/V laid out [B][H][S][D]; attn out [B][S][H][D]
__device__ float g_q[BSZ*HSZ*SSZ*DSZ];
__device__ float g_k[BSZ*HSZ*SSZ*DSZ];
__device__ float g_v[BSZ*HSZ*SSZ*DSZ];
__device__ float g_attn[BSZ*SSZ*HSZ*DSZ];

__device__ __forceinline__ uint32_t f2tf32(float x) {
    uint32_t r;
    asm("cvt.rna.tf32.f32 %0, %1;" : "=r"(r) : "f"(x));
    return r;
}

__device__ __forceinline__ void mma_tf32(float& d0, float& d1, float& d2, float& d3,
                                         uint32_t a0, uint32_t a1, uint32_t a2, uint32_t a3,
                                         uint32_t b0, uint32_t b1) {
    asm volatile(
        "mma.sync.aligned.m16n8k8.row.col.f32.tf32.tf32.f32 "
        "{%0,%1,%2,%3},{%4,%5,%6,%7},{%8,%9},{%0,%1,%2,%3};"
        : "+f"(d0), "+f"(d1), "+f"(d2), "+f"(d3)
        : "r"(a0), "r"(a1), "r"(a2), "r"(a3), "r"(b0), "r"(b1));
}

__device__ __forceinline__ void mma_bf16(float& d0, float& d1, float& d2, float& d3,
                                         uint32_t a0, uint32_t a1, uint32_t a2, uint32_t a3,
                                         uint32_t b0, uint32_t b1) {
    asm volatile(
        "mma.sync.aligned.m16n8k16.row.col.f32.bf16.bf16.f32 "
        "{%0,%1,%2,%3},{%4,%5,%6,%7},{%8,%9},{%0,%1,%2,%3};"
        : "+f"(d0), "+f"(d1), "+f"(d2), "+f"(d3)
        : "r"(a0), "r"(a1), "r"(a2), "r"(a3), "r"(b0), "r"(b1));
}

// Split (x0, x1) -> hi pack {bf16(x1):bf16(x0)} and lo pack of the residuals.
__device__ __forceinline__ void bsplit2(float x0, float x1, uint32_t& hi, uint32_t& lo) {
    uint32_t h;
    asm("cvt.rn.bf16x2.f32 %0, %1, %2;" : "=r"(h) : "f"(x1), "f"(x0));
    float h1 = __uint_as_float(h & 0xFFFF0000u);
    float h0 = __uint_as_float(h << 16);
    float r0 = x0 - h0;
    float r1 = x1 - h1;
    asm("cvt.rn.bf16x2.f32 %0, %1, %2;" : "=r"(lo) : "f"(r1), "f"(r0));
    hi = h;
}

__device__ __forceinline__ void ldsm_x4(uint32_t& r0, uint32_t& r1, uint32_t& r2, uint32_t& r3,
                                        uint32_t addr) {
    asm volatile("ldmatrix.sync.aligned.m8n8.x4.shared.b16 {%0,%1,%2,%3}, [%4];"
        : "=r"(r0), "=r"(r1), "=r"(r2), "=r"(r3) : "r"(addr));
}
__device__ __forceinline__ void ldsm_x4_t(uint32_t& r0, uint32_t& r1, uint32_t& r2, uint32_t& r3,
                                          uint32_t addr) {
    asm volatile("ldmatrix.sync.aligned.m8n8.x4.trans.shared.b16 {%0,%1,%2,%3}, [%4];"
        : "=r"(r0), "=r"(r1), "=r"(r2), "=r"(r3) : "r"(addr));
}

// ---------------------------------------------------------------------------
// 3xBF16 GEMM, R17: R12 skeleton with 512 threads (16 warps as 4m x 4n,
// warp tile 32x64), BM=128, BN=256, in-kernel split, ping-pong, 1 sync/chunk.
// mode 0: N=3072, scatter into g_q/g_k/g_v with q-scale (QKV projection)
// mode 1: N=1024, A := g_attn, plain write to out (output projection)
// ---------------------------------------------------------------------------
__global__ __launch_bounds__(512) void gemm_tc_kernel(
    const float* __restrict__ A, const float* __restrict__ Bm,
    const float* __restrict__ bias, float* __restrict__ out,
    const int* __restrict__ lidx, int N, int mode)
{
    const int K = 1024;
    extern __shared__ char smg[];
    uint32_t smB = (uint32_t)__cvta_generic_to_shared(smg);

    const float* Ap = (mode == 1) ? (const float*)g_attn : A;

    int tid = threadIdx.x;
    int bm = blockIdx.y;
    int bn = blockIdx.x;
    int lane = tid & 31, warp = tid >> 5;   // warp 0..15
    int wm = (warp >> 2) * 32;              // 4 m-warps (32 rows each)
    int wn = (warp & 3) * 64;               // 4 n-warps (64 cols each)
    int r = lane >> 2;
    int c = lane & 3;

    const float* Ab = Ap + (size_t)bm * 128 * K;
    const float* Bb = Bm + (size_t)bn * 256;

    // gmem load assignment (fp32)
    int aM = tid >> 2;              // 0..127
    int aK = (tid & 3) * 8;         // 0,8,16,24  (8 floats per thread)
    int bK = tid >> 4;              // 0..31
    int bN = (tid & 15) * 16;       // 0..240     (16 floats per thread)

    int lr   = lane & 7;
    int lm8  = (lane >> 3) & 1;
    int lhi  = (lane >> 4) & 1;
    int aRowL = wm + lr + lm8 * 8;
    int bRowL = lr + lm8 * 8;

    // per-thread store byte offsets (bf16, within a stage)
    uint32_t aStO = (uint32_t)aM * 80u + (uint32_t)aK * 2u;
    uint32_t bStO = (uint32_t)bK * 528u + (uint32_t)bN * 2u;

    float acc[2][8][4];             // [mi m16-tile][ni n8-tile][e]
    #pragma unroll
    for (int mi = 0; mi < 2; mi++)
        #pragma unroll
        for (int ni = 0; ni < 8; ni++)
            #pragma unroll
            for (int e = 0; e < 4; e++) acc[mi][ni][e] = 0.f;

    float4 aPref[2];
    float4 bPref[4];
    #pragma unroll
    for (int j = 0; j < 2; j++)
        aPref[j] = *(const float4*)(Ab + (size_t)aM * K + aK + j * 4);
    #pragma unroll
    for (int j = 0; j < 4; j++)
        bPref[j] = *(const float4*)(Bb + (size_t)bK * N + bN + j * 4);

    auto commit = [&](int s) {
        char* st = smg + s * G_STG;
        uint32_t hp[4], lp[4];
        bsplit2(aPref[0].x, aPref[0].y, hp[0], lp[0]);
        bsplit2(aPref[0].z, aPref[0].w, hp[1], lp[1]);
        bsplit2(aPref[1].x, aPref[1].y, hp[2], lp[2]);
        bsplit2(aPref[1].z, aPref[1].w, hp[3], lp[3]);
        *(uint4*)(st + aStO)         = make_uint4(hp[0], hp[1], hp[2], hp[3]);
        *(uint4*)(st + G_ALO + aStO) = make_uint4(lp[0], lp[1], lp[2], lp[3]);
        #pragma unroll
        for (int j = 0; j < 2; j++) {
            uint32_t h0, l0, h1, l1, h2, l2, h3, l3;
            bsplit2(bPref[2*j].x, bPref[2*j].y, h0, l0);
            bsplit2(bPref[2*j].z, bPref[2*j].w, h1, l1);
            bsplit2(bPref[2*j+1].x, bPref[2*j+1].y, h2, l2);
            bsplit2(bPref[2*j+1].z, bPref[2*j+1].w, h3, l3);
            *(uint4*)(st + G_BHI + bStO + j * 16) = make_uint4(h0, h1, h2, h3);
            *(uint4*)(st + G_BLO + bStO + j * 16) = make_uint4(l0, l1, l2, l3);
        }
    };

    commit(0);
    __syncthreads();

    const int NCHUNK = K / 32;      // 32
    for (int cI = 0; cI < NCHUNK; cI++) {
        if (cI + 1 < NCHUNK) {
            int k0 = (cI + 1) * 32;
            #pragma unroll
            for (int j = 0; j < 2; j++)
                aPref[j] = *(const float4*)(Ab + (size_t)aM * K + k0 + aK + j * 4);
            #pragma unroll
            for (int j = 0; j < 4; j++)
                bPref[j] = *(const float4*)(Bb + (size_t)(k0 + bK) * N + bN + j * 4);
        }

        uint32_t stO = smB + (uint32_t)(cI & 1) * G_STG;
        #pragma unroll
        for (int ks = 0; ks < 2; ks++) {
            uint32_t ahi[2][4], alo[2][4];
            #pragma unroll
            for (int mi = 0; mi < 2; mi++) {
                uint32_t off = (uint32_t)(aRowL + mi * 16) * 80u + ks * 32u + lhi * 16u;
                ldsm_x4(ahi[mi][0], ahi[mi][1], ahi[mi][2], ahi[mi][3], stO + off);
                ldsm_x4(alo[mi][0], alo[mi][1], alo[mi][2], alo[mi][3], stO + G_ALO + off);
            }
            #pragma unroll
            for (int p = 0; p < 4; p++) {
                uint32_t bhi[4], blo[4];
                uint32_t off = (uint32_t)(ks * 16 + bRowL) * 528u
                             + (uint32_t)(wn + p * 16 + lhi * 8) * 2u;
                ldsm_x4_t(bhi[0], bhi[1], bhi[2], bhi[3], stO + G_BHI + off);
                ldsm_x4_t(blo[0], blo[1], blo[2], blo[3], stO + G_BLO + off);
                #pragma unroll
                for (int mi = 0; mi < 2; mi++)
                    #pragma unroll
                    for (int q = 0; q < 2; q++) {
                        float* d = acc[mi][2 * p + q];
                        uint32_t b0h = bhi[2*q], b1h = bhi[2*q+1];
                        uint32_t b0l = blo[2*q], b1l = blo[2*q+1];
                        mma_bf16(d[0], d[1], d[2], d[3],
                                 ahi[mi][0], ahi[mi][1], ahi[mi][2], ahi[mi][3], b0h, b1h);
                        mma_bf16(d[0], d[1], d[2], d[3],
                                 ahi[mi][0], ahi[mi][1], ahi[mi][2], ahi[mi][3], b0l, b1l);
                        mma_bf16(d[0], d[1], d[2], d[3],
                                 alo[mi][0], alo[mi][1], alo[mi][2], alo[mi][3], b0h, b1h);
                    }
            }
        }

        if (cI + 1 < NCHUNK)
            commit((cI + 1) & 1);
        __syncthreads();
    }

    // Epilogue. acc elem e: row = r + (e>>1)*8, col = c*2 + (e&1)
    if (mode == 0) {
        float scale = 0.125f / (float)(lidx[0] + 1);
        #pragma unroll
        for (int mi = 0; mi < 2; mi++) {
            #pragma unroll
            for (int ni = 0; ni < 8; ni++) {
                #pragma unroll
                for (int e = 0; e < 4; e++) {
                    int m = bm * 128 + wm + mi * 16 + r + (e >> 1) * 8;
                    int n = bn * 256 + wn + ni * 8 + c * 2 + (e & 1);
                    float v = acc[mi][ni][e] + bias[n];
                    int b = m >> 11, s = m & 2047;
                    int t = n >> 10;
                    int hd = n & 1023;
                    int h = hd >> 6, d = hd & 63;
                    size_t idx = ((size_t)(b * HSZ + h) * SSZ + s) * DSZ + d;
                    if (t == 0)      g_q[idx] = v * scale;
                    else if (t == 1) g_k[idx] = v;
                    else             g_v[idx] = v;
                }
            }
        }
    } else {
        #pragma unroll
        for (int mi = 0; mi < 2; mi++) {
            #pragma unroll
            for (int ni = 0; ni < 8; ni++) {
                #pragma unroll
                for (int e = 0; e < 4; e++) {
                    int m = bm * 128 + wm + mi * 16 + r + (e >> 1) * 8;
                    int n = bn * 256 + wn + ni * 8 + c * 2 + (e & 1);
                    out[(size_t)m * N + n] = acc[mi][ni][e] + bias[n];
                }
            }
        }
    }
}

// ---------------------------------------------------------------------------
// Tensor-core flash attention (exact R13 champion version).
// ---------------------------------------------------------------------------
__global__ __launch_bounds__(256, 1) void attn_tc_kernel()
{
    extern __shared__ char smc[];
    uint32_t smB = (uint32_t)__cvta_generic_to_shared(smc);

    int bh = blockIdx.y;
    int qb = 15 - blockIdx.x;
    int q0 = qb * 128;

    const float* qp = g_q + (size_t)bh * SSZ * DSZ + (size_t)q0 * DSZ;
    const float* kb = g_k + (size_t)bh * SSZ * DSZ;
    const float* vb = g_v + (size_t)bh * SSZ * DSZ;

    int tid = threadIdx.x, lane = tid & 31, warp = tid >> 5;
    int r = lane >> 2, c = lane & 3;
    int wr0 = warp * 16;
    int lr  = lane & 7;
    int lm8 = (lane >> 3) & 1;
    int lhi = (lane >> 4) & 1;
    int g   = lane >> 3;
    int kdn = (g & 1) * 8;
    int kdk = (g >> 1) * 4;

    {
        float (*Qs)[QPAD] = (float(*)[QPAD])smc;
        for (int i = tid; i < 128 * 16; i += 256) {
            int row = i >> 4, col4 = (i & 15) * 4;
            *(float4*)&Qs[row][col4] = *(const float4*)(qp + row * 64 + col4);
        }
        __syncthreads();
    }
    uint32_t qa[8][4];
    {
        float (*Qs)[QPAD] = (float(*)[QPAD])smc;
        #pragma unroll
        for (int ks = 0; ks < 8; ks++) {
            int k8 = ks * 8;
            qa[ks][0] = f2tf32(Qs[wr0 + r][k8 + c]);
            qa[ks][1] = f2tf32(Qs[wr0 + r + 8][k8 + c]);
            qa[ks][2] = f2tf32(Qs[wr0 + r][k8 + c + 4]);
            qa[ks][3] = f2tf32(Qs[wr0 + r + 8][k8 + c + 4]);
        }
        __syncthreads();
    }

    float m0 = -1e30f, m1 = -1e30f, l0 = 0.f, l1 = 0.f;
    float o[8][4];
    #pragma unroll
    for (int ni = 0; ni < 8; ni++)
        #pragma unroll
        for (int e = 0; e < 4; e++) o[ni][e] = 0.f;

    int qrow0 = q0 + wr0 + r;
    int qrow1 = qrow0 + 8;

    int rowT[4], colT[4];
    #pragma unroll
    for (int j = 0; j < 4; j++) {
        int i = tid + j * 256;
        rowT[j] = i >> 4;
        colT[j] = (i & 15) * 4;
    }

    float4 kPref[4], vPref[4];

    auto commitKV = [&](int s) {
        char* st = smc + s * A_STG;
        #pragma unroll
        for (int j = 0; j < 4; j++) {
            uint4 kt4;
            kt4.x = f2tf32(kPref[j].x); kt4.y = f2tf32(kPref[j].y);
            kt4.z = f2tf32(kPref[j].z); kt4.w = f2tf32(kPref[j].w);
            *(uint4*)(st + (uint32_t)rowT[j] * (KPADF*4) + (uint32_t)colT[j] * 4) = kt4;

            uint32_t h0, l0r, h1, l1r;
            bsplit2(vPref[j].x, vPref[j].y, h0, l0r);
            bsplit2(vPref[j].z, vPref[j].w, h1, l1r);
            *(uint2*)(st + A_VHI + (uint32_t)rowT[j] * (VPADB*2) + (uint32_t)colT[j] * 2) = make_uint2(h0, h1);
            *(uint2*)(st + A_VLO + (uint32_t)rowT[j] * (VPADB*2) + (uint32_t)colT[j] * 2) = make_uint2(l0r, l1r);
        }
    };

    {
        #pragma unroll
        for (int j = 0; j < 4; j++) {
            kPref[j] = *(const float4*)(kb + rowT[j] * 64 + colT[j]);
            vPref[j] = *(const float4*)(vb + rowT[j] * 64 + colT[j]);
        }
        commitKV(0);
    }
    __syncthreads();

    int ntiles = (qb + 1) * 2;
    for (int kt = 0; kt < ntiles; kt++) {
        if (kt + 1 < ntiles) {
            const float* kp = kb + (size_t)(kt + 1) * 64 * DSZ;
            const float* vp = vb + (size_t)(kt + 1) * 64 * DSZ;
            #pragma unroll
            for (int j = 0; j < 4; j++) {
                kPref[j] = *(const float4*)(kp + rowT[j] * 64 + colT[j]);
                vPref[j] = *(const float4*)(vp + rowT[j] * 64 + colT[j]);
            }
        }

        uint32_t stO = (uint32_t)(kt & 1) * A_STG;

        float s[8][4];
        #pragma unroll
        for (int ni = 0; ni < 8; ni++)
            #pragma unroll
            for (int e = 0; e < 4; e++) s[ni][e] = 0.f;

        #pragma unroll
        for (int ks = 0; ks < 8; ks++) {
            int k8 = ks * 8;
            #pragma unroll
            for (int np = 0; np < 4; np++) {
                uint32_t kb0, kb1, kb2, kb3;
                uint32_t off = stO + (uint32_t)((np * 16 + kdn + lr) * KPADF + k8 + kdk) * 4u;
                ldsm_x4(kb0, kb1, kb2, kb3, smB + off);
                mma_tf32(s[2*np][0], s[2*np][1], s[2*np][2], s[2*np][3],
                         qa[ks][0], qa[ks][1], qa[ks][2], qa[ks][3], kb0, kb2);
                mma_tf32(s[2*np+1][0], s[2*np+1][1], s[2*np+1][2], s[2*np+1][3],
                         qa[ks][0], qa[ks][1], qa[ks][2], qa[ks][3], kb1, kb3);
            }
        }

        if (kt * 64 + 63 > qrow0) {
            #pragma unroll
            for (int ni = 0; ni < 8; ni++) {
                int key = kt * 64 + ni * 8 + 2 * c;
                if (key     > qrow0) s[ni][0] = -1e30f;
                if (key + 1 > qrow0) s[ni][1] = -1e30f;
                if (key     > qrow1) s[ni][2] = -1e30f;
                if (key + 1 > qrow1) s[ni][3] = -1e30f;
            }
        }

        float mx0 = -1e30f, mx1 = -1e30f;
        #pragma unroll
        for (int ni = 0; ni < 8; ni++) {
            mx0 = fmaxf(mx0, fmaxf(s[ni][0], s[ni][1]));
            mx1 = fmaxf(mx1, fmaxf(s[ni][2], s[ni][3]));
        }
        mx0 = fmaxf(mx0, __shfl_xor_sync(0xffffffffu, mx0, 1));
        mx0 = fmaxf(mx0, __shfl_xor_sync(0xffffffffu, mx0, 2));
        mx1 = fmaxf(mx1, __shfl_xor_sync(0xffffffffu, mx1, 1));
        mx1 = fmaxf(mx1, __shfl_xor_sync(0xffffffffu, mx1, 2));

        float mn0 = fmaxf(m0, mx0), mn1 = fmaxf(m1, mx1);
        float sum0 = 0.f, sum1 = 0.f;
        #pragma unroll
        for (int ni = 0; ni < 8; ni++) {
            float p0 = __expf(s[ni][0] - mn0);
            float p1 = __expf(s[ni][1] - mn0);
            float p2 = __expf(s[ni][2] - mn1);
            float p3 = __expf(s[ni][3] - mn1);
            sum0 += p0 + p1;
            sum1 += p2 + p3;
            uint32_t h, lw;
            int byte0 = A_PHI + (wr0 + r) * (PPADB*2) + (ni * 8 + 2 * c) * 2;
            int byte1 = A_PHI + (wr0 + r + 8) * (PPADB*2) + (ni * 8 + 2 * c) * 2;
            bsplit2(p0, p1, h, lw);
            *(uint32_t*)(smc + byte0) = h;
            *(uint32_t*)(smc + byte0 + (A_PLO - A_PHI)) = lw;
            bsplit2(p2, p3, h, lw);
            *(uint32_t*)(smc + byte1) = h;
            *(uint32_t*)(smc + byte1 + (A_PLO - A_PHI)) = lw;
        }
        sum0 += __shfl_xor_sync(0xffffffffu, sum0, 1);
        sum0 += __shfl_xor_sync(0xffffffffu, sum0, 2);
        sum1 += __shfl_xor_sync(0xffffffffu, sum1, 1);
        sum1 += __shfl_xor_sync(0xffffffffu, sum1, 2);

        float alpha0 = __expf(m0 - mn0);
        float alpha1 = __expf(m1 - mn1);
        l0 = l0 * alpha0 + sum0;  m0 = mn0;
        l1 = l1 * alpha1 + sum1;  m1 = mn1;
        #pragma unroll
        for (int ni = 0; ni < 8; ni++) {
            o[ni][0] *= alpha0; o[ni][1] *= alpha0;
            o[ni][2] *= alpha1; o[ni][3] *= alpha1;
        }
        __syncwarp();

        #pragma unroll
        for (int ks = 0; ks < 4; ks++) {
            uint32_t phf[4], plf[4];
            uint32_t offP = A_PHI + (uint32_t)(wr0 + lr + lm8 * 8) * (PPADB*2)
                          + (uint32_t)(ks * 16 + lhi * 8) * 2u;
            ldsm_x4(phf[0], phf[1], phf[2], phf[3], smB + offP);
            ldsm_x4(plf[0], plf[1], plf[2], plf[3], smB + offP + (A_PLO - A_PHI));

            uint32_t vhf[4][4], vlf[4][4];
            #pragma unroll
            for (int p = 0; p < 4; p++) {
                uint32_t offV = stO + A_VHI + (uint32_t)(ks * 16 + lr + lm8 * 8) * (VPADB*2)
                              + (uint32_t)(p * 16 + lhi * 8) * 2u;
                ldsm_x4_t(vhf[p][0], vhf[p][1], vhf[p][2], vhf[p][3], smB + offV);
                ldsm_x4_t(vlf[p][0], vlf[p][1], vlf[p][2], vlf[p][3], smB + offV + (A_VLO - A_VHI));
            }
            #pragma unroll
            for (int p = 0; p < 4; p++)
                #pragma unroll
                for (int q = 0; q < 2; q++) {
                    float* d = o[2 * p + q];
                    uint32_t b0h = vhf[p][2*q], b1h = vhf[p][2*q+1];
                    uint32_t b0l = vlf[p][2*q], b1l = vlf[p][2*q+1];
                    mma_bf16(d[0], d[1], d[2], d[3],
                             phf[0], phf[1], phf[2], phf[3], b0h, b1h);
                    mma_bf16(d[0], d[1], d[2], d[3],
                             phf[0], phf[1], phf[2], phf[3], b0l, b1l);
                    mma_bf16(d[0], d[1], d[2], d[3],
                             plf[0], plf[1], plf[2], plf[3], b0h, b1h);
                }
        }

        if (kt + 1 < ntiles)
            commitKV((kt + 1) & 1);
        __syncthreads();
    }

    // Epilogue: normalize and write [B][S][H][D]
    int b = bh >> 4, h = bh & 15;
    float inv0 = 1.f / l0, inv1 = 1.f / l1;
    int s0 = q0 + wr0 + r, s1 = s0 + 8;
    size_t base0 = ((size_t)(b * SSZ + s0) * HSZ + h) * DSZ;
    size_t base1 = ((size_t)(b * SSZ + s1) * HSZ + h) * DSZ;
    #pragma unroll
    for (int ni = 0; ni < 8; ni++) {
        int d0 = ni * 8 + 2 * c;
        *(float2*)&g_attn[base0 + d0] = make_float2(o[ni][0] * inv0, o[ni][1] * inv0);
        *(float2*)&g_attn[base1 + d0] = make_float2(o[ni][2] * inv1, o[ni][3] * inv1);
    }
}

extern "C" void kernel_launch(void* const* d_in, const int* in_sizes, int n_in,
                              void* d_out, int out_size)
{
    const float* hidden = (const float*)d_in[0];
    const float* Wqkv  = (const float*)d_in[2];
    const float* bqkv  = (const float*)d_in[3];
    const float* Wproj = (const float*)d_in[4];
    const float* bproj = (const float*)d_in[5];
    const int*   lidx  = (const int*)d_in[6];
    float* out = (float*)d_out;

    cudaFuncSetAttribute(gemm_tc_kernel,
        cudaFuncAttributeMaxDynamicSharedMemorySize, G_TOTAL);
    cudaFuncSetAttribute(attn_tc_kernel,
        cudaFuncAttributeMaxDynamicSharedMemorySize, A_TOTAL);

    // QKV projection: M=8192, N=3072, K=1024  (BN=256 -> 12 n-blocks)
    gemm_tc_kernel<<<dim3(12, 64), 512, G_TOTAL>>>(hidden, Wqkv, bqkv, nullptr, lidx, 3072, 0);
    // Attention: 16 query tiles (128 rows each) x 64 (b,h) pairs
    attn_tc_kernel<<<dim3(16, 64), 256, A_TOTAL>>>();
    // Output projection: M=8192, N=1024, K=1024  (BN=256 -> 4 n-blocks)
    gemm_tc_kernel<<<dim3(4, 64), 512, G_TOTAL>>>(nullptr, Wproj, bproj, out, lidx, 1024, 1);
}